// round 4
// baseline (speedup 1.0000x reference)
#include <cuda_runtime.h>

#define NN 50000
#define EE 800000

// ---------------- scratch (device globals; referenced directly in device code) ----------------
__device__ float g_buf0[NN * 96];   // GEMM output (xs = dinv * XW)
__device__ float g_buf1[NN * 96];   // aggregation output / next layer input
__device__ int   g_deg[NN];
__device__ float g_dinv[NN];
__device__ int   g_off[NN + 1];
__device__ int   g_cur[NN];
__device__ int   g_esrc[EE];
__device__ int   g_bsum[128];

// ---------------- CSR build ----------------
__global__ void k_zero_deg() {
    int i = blockIdx.x * blockDim.x + threadIdx.x;
    if (i < NN) g_deg[i] = 0;
}

__global__ void k_count(const int* __restrict__ dst) {
    int e = blockIdx.x * blockDim.x + threadIdx.x;
    if (e < EE) atomicAdd(&g_deg[dst[e]], 1);
}

__global__ void k_scan1() {
    __shared__ int sh[512];
    int t = threadIdx.x;
    int i = blockIdx.x * 512 + t;
    int v = (i < NN) ? g_deg[i] : 0;
    sh[t] = v;
    for (int o = 1; o < 512; o <<= 1) {
        __syncthreads();
        int tmp = (t >= o) ? sh[t - o] : 0;
        __syncthreads();
        sh[t] += tmp;
    }
    __syncthreads();
    if (i < NN) g_off[i] = sh[t] - v;       // exclusive within block
    if (t == 511) g_bsum[blockIdx.x] = sh[511];
}

__global__ void k_scan2(int nb) {
    if (threadIdx.x == 0) {
        int acc = 0;
        for (int b = 0; b < nb; b++) { int v = g_bsum[b]; g_bsum[b] = acc; acc += v; }
    }
}

__global__ void k_scan3() {
    int i = blockIdx.x * blockDim.x + threadIdx.x;
    if (i < NN) {
        int o = g_off[i] + g_bsum[i >> 9];
        g_off[i] = o;
        g_cur[i] = o;
        g_dinv[i] = rsqrtf((float)(g_deg[i] + 1));   // +1 self-loop
    }
    if (i == 0) g_off[NN] = EE;
}

__global__ void k_fill(const int* __restrict__ src, const int* __restrict__ dst) {
    int e = blockIdx.x * blockDim.x + threadIdx.x;
    if (e < EE) {
        int d = dst[e];
        int p = atomicAdd(&g_cur[d], 1);
        g_esrc[p] = src[e];
    }
}

// ---------------- GEMM: g_buf0[row,:] = dinv[row] * (relu?(X[row,:]) @ W) ----------------
// X is external input when in_sel==0, else g_buf1.
// 32 rows per block (8 warps x 4 rows), K-chunked into 64, W + X tiles in smem.
template <int FOUT>
__global__ void k_gemm(const float* __restrict__ Xext, const float* __restrict__ W,
                       int in_sel, int K, int relu_in) {
    const float* X = (in_sel == 0) ? Xext : (const float*)g_buf1;
    __shared__ float Ws[64 * FOUT];
    __shared__ float Xs[32 * 64];
    const int t = threadIdx.x, lane = t & 31, warp = t >> 5;
    const int row0 = blockIdx.x * 32;
    constexpr int CJ = FOUT / 32;
    float acc[4][CJ];
#pragma unroll
    for (int r = 0; r < 4; r++)
#pragma unroll
        for (int j = 0; j < CJ; j++) acc[r][j] = 0.f;

    for (int k0 = 0; k0 < K; k0 += 64) {
        int kc = min(64, K - k0);
        __syncthreads();
        for (int i = t; i < kc * FOUT; i += 256) {
            int kk = i / FOUT, c = i - kk * FOUT;
            Ws[kk * FOUT + c] = W[(k0 + kk) * FOUT + c];
        }
        for (int i = t; i < 32 * kc; i += 256) {
            int r = i / kc, kk = i - r * kc;
            int row = row0 + r;
            float v = 0.f;
            if (row < NN) {
                v = X[row * K + k0 + kk];
                if (relu_in) v = fmaxf(v, 0.f);
            }
            Xs[r * 64 + kk] = v;
        }
        __syncthreads();
        const float* xr = &Xs[warp * 4 * 64];
        for (int kk = 0; kk < kc; kk++) {
            float a0 = xr[kk], a1 = xr[64 + kk], a2 = xr[128 + kk], a3 = xr[192 + kk];
#pragma unroll
            for (int j = 0; j < CJ; j++) {
                float w = Ws[kk * FOUT + lane + 32 * j];
                acc[0][j] = fmaf(a0, w, acc[0][j]);
                acc[1][j] = fmaf(a1, w, acc[1][j]);
                acc[2][j] = fmaf(a2, w, acc[2][j]);
                acc[3][j] = fmaf(a3, w, acc[3][j]);
            }
        }
    }
#pragma unroll
    for (int r = 0; r < 4; r++) {
        int row = row0 + warp * 4 + r;
        if (row < NN) {
            float s = g_dinv[row];
#pragma unroll
            for (int j = 0; j < CJ; j++)
                g_buf0[row * FOUT + lane + 32 * j] = s * acc[r][j];
        }
    }
}

// ---------------- aggregation: out[d] = dinv[d]*(xs[d] + sum_{src} xs[src]) + b ----------------
// 96-wide: warp per node, 24 lanes x float4. Reads g_buf0, writes g_buf1.
__global__ void k_agg96(const float* __restrict__ bias) {
    int wid = (blockIdx.x * blockDim.x + threadIdx.x) >> 5;
    int lane = threadIdx.x & 31;
    if (wid >= NN) return;
    int d = wid;
    int beg = g_off[d], end = g_off[d + 1];
    const float4* x4 = (const float4*)g_buf0;
    float4 acc = make_float4(0.f, 0.f, 0.f, 0.f);
    if (lane < 24) acc = x4[d * 24 + lane];   // self-loop
    for (int e = beg; e < end; e++) {
        int s = g_esrc[e];
        if (lane < 24) {
            float4 v = __ldg(&x4[s * 24 + lane]);
            acc.x += v.x; acc.y += v.y; acc.z += v.z; acc.w += v.w;
        }
    }
    if (lane < 24) {
        float sc = g_dinv[d];
        float4 b = ((const float4*)bias)[lane];
        float4 o;
        o.x = sc * acc.x + b.x; o.y = sc * acc.y + b.y;
        o.z = sc * acc.z + b.z; o.w = sc * acc.w + b.w;
        ((float4*)g_buf1)[d * 24 + lane] = o;
    }
}

// 32-wide: warp per node, 4 edge-groups of 8 lanes (float4), shfl reduce across groups.
// Reads g_buf0, writes external out.
__global__ void k_agg32(const float* __restrict__ bias, float* __restrict__ out) {
    int wid = (blockIdx.x * blockDim.x + threadIdx.x) >> 5;
    int lane = threadIdx.x & 31;
    if (wid >= NN) return;
    int d = wid;
    int grp = lane >> 3, fl = lane & 7;
    const float4* x4 = (const float4*)g_buf0;
    float4 acc = make_float4(0.f, 0.f, 0.f, 0.f);
    if (grp == 0) acc = x4[d * 8 + fl];       // self-loop
    int beg = g_off[d], end = g_off[d + 1];
    for (int e = beg + grp; e < end; e += 4) {
        int s = g_esrc[e];
        float4 v = __ldg(&x4[s * 8 + fl]);
        acc.x += v.x; acc.y += v.y; acc.z += v.z; acc.w += v.w;
    }
#pragma unroll
    for (int o = 8; o <= 16; o <<= 1) {
        acc.x += __shfl_xor_sync(0xFFFFFFFF, acc.x, o);
        acc.y += __shfl_xor_sync(0xFFFFFFFF, acc.y, o);
        acc.z += __shfl_xor_sync(0xFFFFFFFF, acc.z, o);
        acc.w += __shfl_xor_sync(0xFFFFFFFF, acc.w, o);
    }
    if (lane < 8) {
        float sc = g_dinv[d];
        float4 b = ((const float4*)bias)[fl];
        float4 o;
        o.x = sc * acc.x + b.x; o.y = sc * acc.y + b.y;
        o.z = sc * acc.z + b.z; o.w = sc * acc.w + b.w;
        ((float4*)out)[d * 8 + fl] = o;
    }
}

// ---------------- log_softmax over 32 classes: warp per node ----------------
__global__ void k_lsm(float* __restrict__ out) {
    int wid = (blockIdx.x * blockDim.x + threadIdx.x) >> 5;
    int lane = threadIdx.x & 31;
    if (wid >= NN) return;
    float v = out[wid * 32 + lane];
    float m = v;
#pragma unroll
    for (int o = 16; o >= 1; o >>= 1) m = fmaxf(m, __shfl_xor_sync(0xFFFFFFFF, m, o));
    float e = expf(v - m);
    float s = e;
#pragma unroll
    for (int o = 16; o >= 1; o >>= 1) s += __shfl_xor_sync(0xFFFFFFFF, s, o);
    out[wid * 32 + lane] = v - m - logf(s);
}

// ---------------- launch ----------------
extern "C" void kernel_launch(void* const* d_in, const int* in_sizes, int n_in,
                              void* d_out, int out_size) {
    const float* x  = (const float*)d_in[0];
    const int*   ei = (const int*)d_in[1];     // JAX x64 disabled -> int32
    const float* W1 = (const float*)d_in[2];
    const float* b1 = (const float*)d_in[3];
    const float* W2 = (const float*)d_in[4];
    const float* b2 = (const float*)d_in[5];
    const float* W3 = (const float*)d_in[6];
    const float* b3 = (const float*)d_in[7];
    float* out = (float*)d_out;

    const int* src = ei;
    const int* dst = ei + EE;

    const int NB_SCAN = (NN + 511) / 512;

    k_zero_deg<<<(NN + 255) / 256, 256>>>();
    k_count<<<(EE + 255) / 256, 256>>>(dst);
    k_scan1<<<NB_SCAN, 512>>>();
    k_scan2<<<1, 32>>>(NB_SCAN);
    k_scan3<<<(NN + 255) / 256, 256>>>();
    k_fill<<<(EE + 255) / 256, 256>>>(src, dst);

    const int GB = (NN + 31) / 32;           // gemm blocks
    const int AB = (NN * 32 + 255) / 256;    // warp-per-node blocks

    // layer 1: x[50000,128] @ W1[128,96]
    k_gemm<96><<<GB, 256>>>(x, W1, 0, 128, 0);
    k_agg96<<<AB, 256>>>(b1);
    // layer 2: relu(h1) @ W2[96,96]
    k_gemm<96><<<GB, 256>>>(x, W2, 1, 96, 1);
    k_agg96<<<AB, 256>>>(b2);
    // layer 3: relu(h2) @ W3[96,32]
    k_gemm<32><<<GB, 256>>>(x, W3, 1, 96, 1);
    k_agg32<<<AB, 256>>>(b3, out);

    k_lsm<<<AB, 256>>>(out);
}